// round 10
// baseline (speedup 1.0000x reference)
#include <cuda_runtime.h>
#include <cuda_fp16.h>
#include <cstdint>
#include <math.h>

#define Bb 8
#define SS 2048
#define DD 1024
#define HH 16
#define DHH 64
#define MM (Bb * SS)
#define SCALE 0.125f
#define NCH 8               // S-chunks for pooling kernels
#define CHS (SS / NCH)      // 256

// ---------------- helpers ---------------------------------------------------
__device__ __forceinline__ uint32_t smem_to_u32(const void* p) {
    uint32_t a;
    asm("{ .reg .u64 t; cvta.to.shared.u64 t, %1; cvt.u32.u64 %0, t; }"
        : "=r"(a) : "l"(p));
    return a;
}
__device__ __forceinline__ void ldsm_x4(uint32_t* r, uint32_t addr) {
    asm volatile("ldmatrix.sync.aligned.m8n8.x4.shared.b16 {%0,%1,%2,%3}, [%4];"
        : "=r"(r[0]), "=r"(r[1]), "=r"(r[2]), "=r"(r[3]) : "r"(addr));
}
__device__ __forceinline__ void mma16816(float* c, const uint32_t* a,
                                         uint32_t b0, uint32_t b1) {
    asm volatile("mma.sync.aligned.m16n8k16.row.col.f32.f16.f16.f32 "
        "{%0,%1,%2,%3}, {%4,%5,%6,%7}, {%8,%9}, {%0,%1,%2,%3};"
        : "+f"(c[0]), "+f"(c[1]), "+f"(c[2]), "+f"(c[3])
        : "r"(a[0]), "r"(a[1]), "r"(a[2]), "r"(a[3]), "r"(b0), "r"(b1));
}
__device__ __forceinline__ void cp_async16(uint32_t saddr, const void* gaddr) {
    asm volatile("cp.async.cg.shared.global [%0], [%1], 16;"
        :: "r"(saddr), "l"(gaddr));
}
#define CP_COMMIT() asm volatile("cp.async.commit_group;" ::: "memory")
#define CP_WAIT_1() asm volatile("cp.async.wait_group 1;" ::: "memory")
#define CP_WAIT_0() asm volatile("cp.async.wait_group 0;" ::: "memory")

// ---------------- scratch (device globals) ---------------------------------
__device__ float g_q[(size_t)MM * DD];
__device__ float g_k[(size_t)MM * DD];
__device__ float g_qlt[Bb * HH * SS];           // q logits, [bh][s]
__device__ float g_part[Bb * HH * NCH * DHH];   // pool partials
__device__ float g_mstat[Bb * HH * NCH * 2];    // per-chunk (max, expsum)
__device__ float g_pq[Bb * HH * DHH];
__device__ float g_pk[Bb * HH * DHH];
__device__ __half g_hsh[(size_t)MM * DD];
__device__ __half g_a3h[(size_t)MM * DD];
__device__ __half g_wq[DD * DD];
__device__ __half g_wk[DD * DD];
__device__ __half g_wt[DD * DD];

// ---------------- conversion: fp32 -> fp16 (optional pk multiply) ----------
template <int MUL>
__global__ void __launch_bounds__(256)
conv_half(const float* __restrict__ X, const float* __restrict__ pk,
          __half* __restrict__ out)
{
    size_t e = (size_t)blockIdx.x * 256 + threadIdx.x;  // float4 index
    float4 v = ((const float4*)X)[e];
    if (MUL) {
        size_t row = e >> 8;               // e / (DD/4)
        int batch = (int)(row >> 11);      // row / SS
        int col4 = (int)(e & 255);
        float4 p = ((const float4*)(pk + (size_t)batch * DD))[col4];
        v.x *= p.x; v.y *= p.y; v.z *= p.z; v.w *= p.w;
    }
    __half hv[4];
    hv[0] = __float2half_rn(v.x); hv[1] = __float2half_rn(v.y);
    hv[2] = __float2half_rn(v.z); hv[3] = __float2half_rn(v.w);
    ((uint2*)out)[e] = *(uint2*)hv;
}

// ---------------- conversion: weight transpose to fp16 ---------------------
__global__ void __launch_bounds__(256)
conv_w(const float* __restrict__ W, __half* __restrict__ wt)
{
    __shared__ float s[32][33];
    int n0 = blockIdx.x * 32, k0 = blockIdx.y * 32;
    int tx = threadIdx.x & 31, ty = threadIdx.x >> 5;  // 32 x 8
#pragma unroll
    for (int i = 0; i < 4; i++) {
        int r = ty + i * 8;
        s[r][tx] = W[(size_t)(k0 + r) * DD + n0 + tx];
    }
    __syncthreads();
#pragma unroll
    for (int i = 0; i < 4; i++) {
        int r = ty + i * 8;
        wt[(size_t)(n0 + r) * DD + k0 + tx] = __float2half_rn(s[tx][r]);
    }
}

// ---------------- HMMA GEMM: C[M,N] = A @ B^T + bias -----------------------
// 128x256x32 CTA tile, 256 thr = 8 warps of 64x64 (2 m x 4 n).
// cp.async 3-stage ring.
constexpr int PITCH = 80;                  // bytes per 32-elem fp16 row
constexpr int TILEA = 128 * PITCH;         // 10240
constexpr int TILEBB = 256 * PITCH;        // 20480
constexpr int STAGEB = TILEA + TILEBB;     // 30720
constexpr int SMEMB = 3 * STAGEB;          // 92160
constexpr int NKT = 32;

__global__ void __launch_bounds__(256, 1)
gemm_tc(const __half* __restrict__ Ah, const __half* __restrict__ Bw,
        const float* __restrict__ bias, const float* __restrict__ resid,
        float* __restrict__ C, int addResid)
{
    extern __shared__ char smem[];
    const uint32_t sb = smem_to_u32(smem);
    const int tid = threadIdx.x, wid = tid >> 5, lane = tid & 31;
    const int warp_m = wid & 1, warp_n = wid >> 1;   // 2 x 4 warps, 64x64 each
    const int n0 = blockIdx.x * 256;
    const int m0 = blockIdx.y * 128;

    float acc[4][8][4];
#pragma unroll
    for (int i = 0; i < 4; i++)
#pragma unroll
        for (int j = 0; j < 8; j++)
#pragma unroll
            for (int l = 0; l < 4; l++) acc[i][j][l] = 0.0f;

    auto load_stage = [&](int kt, int st) {
        const int k0 = kt * 32;
#pragma unroll
        for (int h = 0; h < 6; h++) {
            int c = tid + h * 256;               // 0..1535
            if (c < 512) {                       // A: 128 rows x 4 chunks
                int row = c >> 2, cc = c & 3;
                uint32_t sa = sb + st * STAGEB + row * PITCH + cc * 16;
                cp_async16(sa, Ah + (size_t)(m0 + row) * DD + k0 + cc * 8);
            } else {                             // B: 256 rows x 4 chunks
                int r = c - 512;
                int row = r >> 2, cc = r & 3;
                uint32_t sa = sb + st * STAGEB + TILEA + row * PITCH + cc * 16;
                cp_async16(sa, Bw + (size_t)(n0 + row) * DD + k0 + cc * 8);
            }
        }
    };

    load_stage(0, 0); CP_COMMIT();
    load_stage(1, 1); CP_COMMIT();

    for (int kt = 0; kt < NKT; kt++) {
        if (kt == NKT - 1) { CP_WAIT_0(); } else { CP_WAIT_1(); }
        __syncthreads();
        if (kt + 2 < NKT) {
            load_stage(kt + 2, (kt + 2) % 3);
            CP_COMMIT();
        }

        const uint32_t s0 = sb + (kt % 3) * STAGEB;
        const int rsel = lane & 15;
        const int hsel = (lane >> 4) * 16;

#pragma unroll
        for (int kp = 0; kp < 2; kp++) {
            const int ksel = hsel + kp * 32;
            uint32_t ah[4][4];
#pragma unroll
            for (int mi = 0; mi < 4; mi++) {
                uint32_t off = (uint32_t)(warp_m * 64 + mi * 16 + rsel) * PITCH + ksel;
                ldsm_x4(ah[mi], s0 + off);
            }
#pragma unroll
            for (int np = 0; np < 4; np++) {
                uint32_t off = (uint32_t)(warp_n * 64 + np * 16 + rsel) * PITCH + ksel;
                uint32_t bh[4];
                ldsm_x4(bh, s0 + TILEA + off);
#pragma unroll
                for (int mi = 0; mi < 4; mi++) {
                    mma16816(acc[mi][2 * np],     ah[mi], bh[0], bh[2]);
                    mma16816(acc[mi][2 * np + 1], ah[mi], bh[1], bh[3]);
                }
            }
        }
    }

    // ---------------- epilogue ----------------
#pragma unroll
    for (int mi = 0; mi < 4; mi++) {
        int row = m0 + warp_m * 64 + mi * 16 + (lane >> 2);
#pragma unroll
        for (int ni = 0; ni < 8; ni++) {
            int col = n0 + warp_n * 64 + ni * 8 + (lane & 3) * 2;
            float b0 = __ldg(bias + col), b1 = __ldg(bias + col + 1);
            float2 v0, v1;
            v0.x = acc[mi][ni][0] + b0;  v0.y = acc[mi][ni][1] + b1;
            v1.x = acc[mi][ni][2] + b0;  v1.y = acc[mi][ni][3] + b1;
            if (addResid) {
                float2 r0 = *(const float2*)(resid + (size_t)row * DD + col);
                float2 r1 = *(const float2*)(resid + (size_t)(row + 8) * DD + col);
                v0.x += r0.x; v0.y += r0.y; v1.x += r1.x; v1.y += r1.y;
            }
            *(float2*)(C + (size_t)row * DD + col) = v0;
            *(float2*)(C + (size_t)(row + 8) * DD + col) = v1;
        }
    }
}

// ---------------- q attention logits (transposed output [bh][s]) -----------
__global__ void __launch_bounds__(256)
qlogits_kernel(const float* __restrict__ Wqa, const float* __restrict__ bqa,
               const float* __restrict__ q, float* __restrict__ qlt)
{
    extern __shared__ float sW[];   // [HH][DD] transposed, 64 KB
    int tid = threadIdx.x;
    for (int i = tid; i < DD * HH; i += 256) {
        int k = i >> 4, h = i & 15;
        sW[h * DD + k] = Wqa[i];
    }
    __syncthreads();

    int warp = tid >> 5, lane = tid & 31;
    for (int rr = 0; rr < 4; rr++) {
        int m = blockIdx.x * 32 + warp * 4 + rr;
        const float* qrow = q + (size_t)m * DD;
        float acc[HH];
#pragma unroll
        for (int h = 0; h < HH; h++) acc[h] = 0.0f;
        for (int k = lane; k < DD; k += 32) {
            float qv = qrow[k];
#pragma unroll
            for (int h = 0; h < HH; h++) acc[h] += qv * sW[h * DD + k];
        }
#pragma unroll
        for (int h = 0; h < HH; h++)
#pragma unroll
            for (int off = 16; off; off >>= 1)
                acc[h] += __shfl_xor_sync(0xffffffffu, acc[h], off);
        if (lane == 0) {
            int b = m >> 11, s = m & (SS - 1);
#pragma unroll
            for (int h = 0; h < HH; h++)
                qlt[((size_t)(b * HH + h)) * SS + s] = acc[h] + bqa[h];
        }
    }
}

// ---------------- pool partial with LOCAL softmax stats --------------------
// grid (NCH, B*H), 256 threads. Writes unnormalized partials + (mloc, esum).
__global__ void __launch_bounds__(256)
poolpart_kernel(const float* __restrict__ lt, const float* __restrict__ mask,
                const float* __restrict__ src, float* __restrict__ part,
                float* __restrict__ mstat)
{
    __shared__ float w[CHS];
    __shared__ float red[256];
    int ch = blockIdx.x, bh = blockIdx.y;
    int b = bh >> 4, h = bh & 15;
    int s0 = ch * CHS;
    int t = threadIdx.x;

    float l = lt[(size_t)bh * SS + s0 + t] * SCALE + mask[(size_t)b * SS + s0 + t];
    red[t] = l; __syncthreads();
    for (int off = 128; off; off >>= 1) {
        if (t < off) red[t] = fmaxf(red[t], red[t + off]);
        __syncthreads();
    }
    float mloc = red[0];
    __syncthreads();

    float e = __expf(l - mloc);
    w[t] = e;
    red[t] = e; __syncthreads();
    for (int off = 128; off; off >>= 1) {
        if (t < off) red[t] += red[t + off];
        __syncthreads();
    }
    float esum = red[0];
    __syncthreads();

    int dh = t & 63, sg = t >> 6;          // 4 s-groups x 64 dh
    const float* src2 = src + ((size_t)(b * SS + s0 + sg)) * DD + h * DHH + dh;
    float acc = 0.0f;
#pragma unroll 16
    for (int i = 0; i < CHS / 4; i++)
        acc += w[sg + 4 * i] * src2[(size_t)4 * i * DD];
    red[t] = acc; __syncthreads();
    if (t < 64)
        part[((size_t)bh * NCH + ch) * DHH + t] =
            red[t] + red[t + 64] + red[t + 128] + red[t + 192];
    if (t == 0) {
        mstat[((size_t)bh * NCH + ch) * 2]     = mloc;
        mstat[((size_t)bh * NCH + ch) * 2 + 1] = esum;
    }
}

// ---------------- fused qk logits + pool partial (k path) ------------------
__global__ void __launch_bounds__(256)
qk_pool_kernel(const float* __restrict__ kx, const float* __restrict__ pq,
               const float* __restrict__ mask, float* __restrict__ part,
               float* __restrict__ mstat)
{
    __shared__ float w[CHS];
    __shared__ float red[256];
    __shared__ float spq[DHH];
    int ch = blockIdx.x, bh = blockIdx.y;
    int b = bh >> 4, h = bh & 15;
    int s0 = ch * CHS;
    int t = threadIdx.x;

    if (t < DHH) spq[t] = pq[(size_t)bh * DHH + t];
    __syncthreads();

    int warp = t >> 5, lane = t & 31;
    float p0 = spq[lane], p1 = spq[lane + 32];
    const float* kb = kx + ((size_t)b * SS) * DD + h * DHH;
#pragma unroll 4
    for (int i = 0; i < 32; i++) {
        int sl = warp * 32 + i;
        const float* kr = kb + (size_t)(s0 + sl) * DD;
        float prt = kr[lane] * p0 + kr[lane + 32] * p1;
#pragma unroll
        for (int off = 16; off; off >>= 1)
            prt += __shfl_xor_sync(0xffffffffu, prt, off);
        if (lane == 0)
            w[sl] = prt * SCALE + mask[(size_t)b * SS + s0 + sl];
    }
    __syncthreads();

    float l = w[t];
    red[t] = l; __syncthreads();
    for (int off = 128; off; off >>= 1) {
        if (t < off) red[t] = fmaxf(red[t], red[t + off]);
        __syncthreads();
    }
    float mloc = red[0];
    __syncthreads();

    float e = __expf(l - mloc);
    w[t] = e;
    red[t] = e; __syncthreads();
    for (int off = 128; off; off >>= 1) {
        if (t < off) red[t] += red[t + off];
        __syncthreads();
    }
    float esum = red[0];
    __syncthreads();

    int dh = t & 63, sg = t >> 6;
    const float* src2 = kb + (size_t)(s0 + sg) * DD + dh;
    float acc = 0.0f;
#pragma unroll 16
    for (int i = 0; i < CHS / 4; i++)
        acc += w[sg + 4 * i] * src2[(size_t)4 * i * DD];
    red[t] = acc; __syncthreads();
    if (t < 64)
        part[((size_t)bh * NCH + ch) * DHH + t] =
            red[t] + red[t + 64] + red[t + 128] + red[t + 192];
    if (t == 0) {
        mstat[((size_t)bh * NCH + ch) * 2]     = mloc;
        mstat[((size_t)bh * NCH + ch) * 2 + 1] = esum;
    }
}

// ---------------- reduce partials with global rescale -----------------------
__global__ void __launch_bounds__(64)
poolred_kernel(const float* __restrict__ part, const float* __restrict__ mstat,
               float* __restrict__ out)
{
    int bh = blockIdx.x, t = threadIdx.x;
    float ml[NCH], ss[NCH];
    float gmax = -1e30f;
#pragma unroll
    for (int c = 0; c < NCH; c++) {
        ml[c] = mstat[((size_t)bh * NCH + c) * 2];
        ss[c] = mstat[((size_t)bh * NCH + c) * 2 + 1];
        gmax = fmaxf(gmax, ml[c]);
    }
    float denom = 0.0f, acc = 0.0f;
#pragma unroll
    for (int c = 0; c < NCH; c++) {
        float f = __expf(ml[c] - gmax);
        denom += ss[c] * f;
        acc += part[((size_t)bh * NCH + c) * DHH + t] * f;
    }
    out[(size_t)bh * DHH + t] = acc / denom;
}

// ---------------------------------------------------------------------------
extern "C" void kernel_launch(void* const* d_in, const int* in_sizes, int n_in,
                              void* d_out, int out_size)
{
    const float* hs   = (const float*)d_in[0];
    const float* mask = (const float*)d_in[1];
    const float* Wq   = (const float*)d_in[2];
    const float* bq   = (const float*)d_in[3];
    const float* Wqa  = (const float*)d_in[4];
    const float* bqa  = (const float*)d_in[5];
    const float* Wk   = (const float*)d_in[6];
    const float* bk   = (const float*)d_in[7];
    const float* Wt   = (const float*)d_in[8];
    const float* bt   = (const float*)d_in[9];
    float* out = (float*)d_out;

    float *q, *k, *qlt, *partp, *mstat, *pq, *pk;
    __half *hsh, *a3h, *wq, *wk, *wt;
    cudaGetSymbolAddress((void**)&q,  g_q);
    cudaGetSymbolAddress((void**)&k,  g_k);
    cudaGetSymbolAddress((void**)&qlt, g_qlt);
    cudaGetSymbolAddress((void**)&partp, g_part);
    cudaGetSymbolAddress((void**)&mstat, g_mstat);
    cudaGetSymbolAddress((void**)&pq, g_pq);
    cudaGetSymbolAddress((void**)&pk, g_pk);
    cudaGetSymbolAddress((void**)&hsh, g_hsh);
    cudaGetSymbolAddress((void**)&a3h, g_a3h);
    cudaGetSymbolAddress((void**)&wq, g_wq);
    cudaGetSymbolAddress((void**)&wk, g_wk);
    cudaGetSymbolAddress((void**)&wt, g_wt);

    cudaFuncSetAttribute(qlogits_kernel,
                         cudaFuncAttributeMaxDynamicSharedMemorySize, 65536);
    cudaFuncSetAttribute(gemm_tc,
                         cudaFuncAttributeMaxDynamicSharedMemorySize, SMEMB);

    const int conv_blocks = (MM * DD / 4) / 256;   // 16384
    dim3 wgrid(DD / 32, DD / 32);
    dim3 ggrid(DD / 256, MM / 128);                // (4, 128) = 512 CTAs
    dim3 pgrid(NCH, Bb * HH);                      // (8, 128)

    // conversions
    conv_half<0><<<conv_blocks, 256>>>(hs, nullptr, hsh);
    conv_w<<<wgrid, 256>>>(Wq, wq);
    conv_w<<<wgrid, 256>>>(Wk, wk);
    conv_w<<<wgrid, 256>>>(Wt, wt);

    // q = hs @ Wq + bq ; k = hs @ Wk + bk
    gemm_tc<<<ggrid, 256, SMEMB>>>(hsh, wq, bq, q, q, 0);
    gemm_tc<<<ggrid, 256, SMEMB>>>(hsh, wk, bk, k, k, 0);

    // pooled_q path
    qlogits_kernel<<<MM / 32, 256, 65536>>>(Wqa, bqa, q, qlt);
    poolpart_kernel<<<pgrid, 256>>>(qlt, mask, q, partp, mstat);
    poolred_kernel<<<Bb * HH, 64>>>(partp, mstat, pq);

    // pooled_k path (fused logits + pool)
    qk_pool_kernel<<<pgrid, 256>>>(k, pq, mask, partp, mstat);
    poolred_kernel<<<Bb * HH, 64>>>(partp, mstat, pk);

    // a3 = q * pk (broadcast over s), convert to fp16
    conv_half<1><<<conv_blocks, 256>>>(q, pk, a3h);

    // out = a3 @ Wt + bt + q
    gemm_tc<<<ggrid, 256, SMEMB>>>(a3h, wt, bt, q, out, 1);
}

// round 11
// speedup vs baseline: 1.1401x; 1.1401x over previous
#include <cuda_runtime.h>
#include <cuda_fp16.h>
#include <cstdint>
#include <math.h>

#define Bb 8
#define SS 2048
#define DD 1024
#define HH 16
#define DHH 64
#define MM (Bb * SS)
#define SCALE 0.125f
#define NCH 8               // S-chunks for pooling kernels
#define CHS (SS / NCH)      // 256

// ---------------- helpers ---------------------------------------------------
__device__ __forceinline__ uint32_t smem_to_u32(const void* p) {
    uint32_t a;
    asm("{ .reg .u64 t; cvta.to.shared.u64 t, %1; cvt.u32.u64 %0, t; }"
        : "=r"(a) : "l"(p));
    return a;
}
__device__ __forceinline__ void ldsm_x4(uint32_t* r, uint32_t addr) {
    asm volatile("ldmatrix.sync.aligned.m8n8.x4.shared.b16 {%0,%1,%2,%3}, [%4];"
        : "=r"(r[0]), "=r"(r[1]), "=r"(r[2]), "=r"(r[3]) : "r"(addr));
}
__device__ __forceinline__ void mma16816(float* c, const uint32_t* a,
                                         uint32_t b0, uint32_t b1) {
    asm volatile("mma.sync.aligned.m16n8k16.row.col.f32.f16.f16.f32 "
        "{%0,%1,%2,%3}, {%4,%5,%6,%7}, {%8,%9}, {%0,%1,%2,%3};"
        : "+f"(c[0]), "+f"(c[1]), "+f"(c[2]), "+f"(c[3])
        : "r"(a[0]), "r"(a[1]), "r"(a[2]), "r"(a[3]), "r"(b0), "r"(b1));
}
__device__ __forceinline__ void cp_async16(uint32_t saddr, const void* gaddr) {
    asm volatile("cp.async.cg.shared.global [%0], [%1], 16;"
        :: "r"(saddr), "l"(gaddr));
}
#define CP_COMMIT() asm volatile("cp.async.commit_group;" ::: "memory")
#define CP_WAIT_1() asm volatile("cp.async.wait_group 1;" ::: "memory")
#define CP_WAIT_0() asm volatile("cp.async.wait_group 0;" ::: "memory")

// ---------------- scratch (device globals) ---------------------------------
__device__ float g_q[(size_t)MM * DD];
__device__ float g_k[(size_t)MM * DD];
__device__ float g_qlt[Bb * HH * SS];           // q logits, [bh][s]
__device__ float g_part[Bb * HH * NCH * DHH];   // pool partials
__device__ float g_mstat[Bb * HH * NCH * 2];    // per-chunk (max, expsum)
__device__ float g_pq[Bb * HH * DHH];
__device__ float g_pk[Bb * HH * DHH];
__device__ __half g_hsh[(size_t)MM * DD];
__device__ __half g_qh[(size_t)MM * DD];        // fp16 copy of q (GEMM1 epi)
__device__ __half g_wq[DD * DD];
__device__ __half g_wk[DD * DD];
__device__ __half g_wt[DD * DD];
__device__ __half g_wtb[(size_t)Bb * DD * DD];  // per-batch pk-scaled Wt^T

// ---------------- conversion: fp32 -> fp16 ----------------------------------
__global__ void __launch_bounds__(256)
conv_half(const float* __restrict__ X, __half* __restrict__ out)
{
    size_t e = (size_t)blockIdx.x * 256 + threadIdx.x;  // float4 index
    float4 v = ((const float4*)X)[e];
    __half hv[4];
    hv[0] = __float2half_rn(v.x); hv[1] = __float2half_rn(v.y);
    hv[2] = __float2half_rn(v.z); hv[3] = __float2half_rn(v.w);
    ((uint2*)out)[e] = *(uint2*)hv;
}

// ---------------- conversion: weight transpose to fp16 ---------------------
__global__ void __launch_bounds__(256)
conv_w(const float* __restrict__ W, __half* __restrict__ wt)
{
    __shared__ float s[32][33];
    int n0 = blockIdx.x * 32, k0 = blockIdx.y * 32;
    int tx = threadIdx.x & 31, ty = threadIdx.x >> 5;  // 32 x 8
#pragma unroll
    for (int i = 0; i < 4; i++) {
        int r = ty + i * 8;
        s[r][tx] = W[(size_t)(k0 + r) * DD + n0 + tx];
    }
    __syncthreads();
#pragma unroll
    for (int i = 0; i < 4; i++) {
        int r = ty + i * 8;
        wt[(size_t)(n0 + r) * DD + k0 + tx] = __float2half_rn(s[tx][r]);
    }
}

// ---------------- per-batch scaled weight: W'_b[n][k] = wt[n][k]*pk[b][k] --
// grid (DD*DD/1024, Bb), 256 threads, 4 halves per thread
__global__ void __launch_bounds__(256)
scale_wt_kernel(const __half* __restrict__ wt, const float* __restrict__ pk,
                __half* __restrict__ wtb)
{
    int b = blockIdx.y;
    size_t e = (size_t)blockIdx.x * 1024 + threadIdx.x * 4;  // half index
    int kk = (int)(e & (DD - 1));                            // k = e % DD
    uint2 raw = *(const uint2*)(wt + e);
    __half* hv = (__half*)&raw;
    float4 p = *(const float4*)(pk + (size_t)b * DD + kk);
    __half ov[4];
    ov[0] = __float2half_rn(__half2float(hv[0]) * p.x);
    ov[1] = __float2half_rn(__half2float(hv[1]) * p.y);
    ov[2] = __float2half_rn(__half2float(hv[2]) * p.z);
    ov[3] = __float2half_rn(__half2float(hv[3]) * p.w);
    *(uint2*)(wtb + (size_t)b * DD * DD + e) = *(uint2*)ov;
}

// ---------------- HMMA GEMM: C[M,N] = A @ B^T + bias -----------------------
// A: [M,K] K-major fp16; B: [N,K] K-major fp16 (optionally per-batch).
// 128x128x32 CTA tile, 256 thr = 8 warps of 32x64, cp.async 3-stage ring.
constexpr int PITCH = 80;                  // bytes per 32-elem fp16 row
constexpr int TILEB = 128 * PITCH;         // 10240
constexpr int STAGEB = 2 * TILEB;          // 20480
constexpr int SMEMB = 3 * STAGEB;          // 61440
constexpr int NKT = 32;

__global__ void __launch_bounds__(256, 2)
gemm_tc(const __half* __restrict__ Ah, const __half* __restrict__ Bw,
        const float* __restrict__ bias, const float* __restrict__ resid,
        float* __restrict__ C, __half* __restrict__ Ch,
        int addResid, int bStrideBatch)
{
    extern __shared__ char smem[];
    const uint32_t sb = smem_to_u32(smem);
    const int tid = threadIdx.x, wid = tid >> 5, lane = tid & 31;
    const int warp_m = wid & 3, warp_n = wid >> 2;
    const int n0 = blockIdx.x * 128;
    const int m0 = blockIdx.y * 128;
    if (bStrideBatch) Bw += (size_t)(m0 >> 11) * bStrideBatch;

    float acc[2][8][4];
#pragma unroll
    for (int i = 0; i < 2; i++)
#pragma unroll
        for (int j = 0; j < 8; j++)
#pragma unroll
            for (int l = 0; l < 4; l++) acc[i][j][l] = 0.0f;

    auto load_stage = [&](int kt, int st) {
        const int k0 = kt * 32;
#pragma unroll
        for (int tile = 0; tile < 2; tile++) {
            const int rowoff = (tile == 0) ? m0 : n0;
            const __half* base = (tile == 0) ? Ah : Bw;
#pragma unroll
            for (int h = 0; h < 2; h++) {
                int c = tid + h * 256;           // 0..511
                int row = c >> 2, cc = c & 3;
                uint32_t sa = sb + st * STAGEB + tile * TILEB + row * PITCH + cc * 16;
                cp_async16(sa, base + (size_t)(rowoff + row) * DD + k0 + cc * 8);
            }
        }
    };

    load_stage(0, 0); CP_COMMIT();
    load_stage(1, 1); CP_COMMIT();

    for (int kt = 0; kt < NKT; kt++) {
        if (kt == NKT - 1) { CP_WAIT_0(); } else { CP_WAIT_1(); }
        __syncthreads();
        if (kt + 2 < NKT) {
            load_stage(kt + 2, (kt + 2) % 3);
            CP_COMMIT();
        }

        const uint32_t s0 = sb + (kt % 3) * STAGEB;
        const int rsel = lane & 15;
        const int hsel = (lane >> 4) * 16;

#pragma unroll
        for (int kp = 0; kp < 2; kp++) {
            uint32_t ah[2][4];
            const int ksel = hsel + kp * 32;
#pragma unroll
            for (int mi = 0; mi < 2; mi++) {
                uint32_t off = (uint32_t)(warp_m * 32 + mi * 16 + rsel) * PITCH + ksel;
                ldsm_x4(ah[mi], s0 + off);
            }
#pragma unroll
            for (int np = 0; np < 4; np++) {
                uint32_t off = (uint32_t)(warp_n * 64 + np * 16 + rsel) * PITCH + ksel;
                uint32_t bh[4];
                ldsm_x4(bh, s0 + TILEB + off);
#pragma unroll
                for (int mi = 0; mi < 2; mi++) {
                    mma16816(acc[mi][2 * np],     ah[mi], bh[0], bh[2]);
                    mma16816(acc[mi][2 * np + 1], ah[mi], bh[1], bh[3]);
                }
            }
        }
    }

    // ---------------- epilogue ----------------
#pragma unroll
    for (int mi = 0; mi < 2; mi++) {
        int row = m0 + warp_m * 32 + mi * 16 + (lane >> 2);
#pragma unroll
        for (int ni = 0; ni < 8; ni++) {
            int col = n0 + warp_n * 64 + ni * 8 + (lane & 3) * 2;
            float b0 = __ldg(bias + col), b1 = __ldg(bias + col + 1);
            float2 v0, v1;
            v0.x = acc[mi][ni][0] + b0;  v0.y = acc[mi][ni][1] + b1;
            v1.x = acc[mi][ni][2] + b0;  v1.y = acc[mi][ni][3] + b1;
            if (addResid) {
                float2 r0 = *(const float2*)(resid + (size_t)row * DD + col);
                float2 r1 = *(const float2*)(resid + (size_t)(row + 8) * DD + col);
                v0.x += r0.x; v0.y += r0.y; v1.x += r1.x; v1.y += r1.y;
            }
            *(float2*)(C + (size_t)row * DD + col) = v0;
            *(float2*)(C + (size_t)(row + 8) * DD + col) = v1;
            if (Ch) {
                *(__half2*)(Ch + (size_t)row * DD + col) =
                    __floats2half2_rn(v0.x, v0.y);
                *(__half2*)(Ch + (size_t)(row + 8) * DD + col) =
                    __floats2half2_rn(v1.x, v1.y);
            }
        }
    }
}

// ---------------- q attention logits (transposed output [bh][s]) -----------
__global__ void __launch_bounds__(256)
qlogits_kernel(const float* __restrict__ Wqa, const float* __restrict__ bqa,
               const float* __restrict__ q, float* __restrict__ qlt)
{
    extern __shared__ float sW[];   // [HH][DD] transposed, 64 KB
    int tid = threadIdx.x;
    for (int i = tid; i < DD * HH; i += 256) {
        int k = i >> 4, h = i & 15;
        sW[h * DD + k] = Wqa[i];
    }
    __syncthreads();

    int warp = tid >> 5, lane = tid & 31;
    for (int rr = 0; rr < 4; rr++) {
        int m = blockIdx.x * 32 + warp * 4 + rr;
        const float* qrow = q + (size_t)m * DD;
        float acc[HH];
#pragma unroll
        for (int h = 0; h < HH; h++) acc[h] = 0.0f;
        for (int k = lane; k < DD; k += 32) {
            float qv = qrow[k];
#pragma unroll
            for (int h = 0; h < HH; h++) acc[h] += qv * sW[h * DD + k];
        }
#pragma unroll
        for (int h = 0; h < HH; h++)
#pragma unroll
            for (int off = 16; off; off >>= 1)
                acc[h] += __shfl_xor_sync(0xffffffffu, acc[h], off);
        if (lane == 0) {
            int b = m >> 11, s = m & (SS - 1);
#pragma unroll
            for (int h = 0; h < HH; h++)
                qlt[((size_t)(b * HH + h)) * SS + s] = acc[h] + bqa[h];
        }
    }
}

// ---------------- pool partial with LOCAL softmax stats --------------------
__global__ void __launch_bounds__(256)
poolpart_kernel(const float* __restrict__ lt, const float* __restrict__ mask,
                const float* __restrict__ src, float* __restrict__ part,
                float* __restrict__ mstat)
{
    __shared__ float w[CHS];
    __shared__ float red[256];
    int ch = blockIdx.x, bh = blockIdx.y;
    int b = bh >> 4, h = bh & 15;
    int s0 = ch * CHS;
    int t = threadIdx.x;

    float l = lt[(size_t)bh * SS + s0 + t] * SCALE + mask[(size_t)b * SS + s0 + t];
    red[t] = l; __syncthreads();
    for (int off = 128; off; off >>= 1) {
        if (t < off) red[t] = fmaxf(red[t], red[t + off]);
        __syncthreads();
    }
    float mloc = red[0];
    __syncthreads();

    float e = __expf(l - mloc);
    w[t] = e;
    red[t] = e; __syncthreads();
    for (int off = 128; off; off >>= 1) {
        if (t < off) red[t] += red[t + off];
        __syncthreads();
    }
    float esum = red[0];
    __syncthreads();

    int dh = t & 63, sg = t >> 6;          // 4 s-groups x 64 dh
    const float* src2 = src + ((size_t)(b * SS + s0 + sg)) * DD + h * DHH + dh;
    float acc = 0.0f;
#pragma unroll 16
    for (int i = 0; i < CHS / 4; i++)
        acc += w[sg + 4 * i] * src2[(size_t)4 * i * DD];
    red[t] = acc; __syncthreads();
    if (t < 64)
        part[((size_t)bh * NCH + ch) * DHH + t] =
            red[t] + red[t + 64] + red[t + 128] + red[t + 192];
    if (t == 0) {
        mstat[((size_t)bh * NCH + ch) * 2]     = mloc;
        mstat[((size_t)bh * NCH + ch) * 2 + 1] = esum;
    }
}

// ---------------- fused qk logits + pool partial (k path) ------------------
__global__ void __launch_bounds__(256)
qk_pool_kernel(const float* __restrict__ kx, const float* __restrict__ pq,
               const float* __restrict__ mask, float* __restrict__ part,
               float* __restrict__ mstat)
{
    __shared__ float w[CHS];
    __shared__ float red[256];
    __shared__ float spq[DHH];
    int ch = blockIdx.x, bh = blockIdx.y;
    int b = bh >> 4, h = bh & 15;
    int s0 = ch * CHS;
    int t = threadIdx.x;

    if (t < DHH) spq[t] = pq[(size_t)bh * DHH + t];
    __syncthreads();

    int warp = t >> 5, lane = t & 31;
    float p0 = spq[lane], p1 = spq[lane + 32];
    const float* kb = kx + ((size_t)b * SS) * DD + h * DHH;
#pragma unroll 4
    for (int i = 0; i < 32; i++) {
        int sl = warp * 32 + i;
        const float* kr = kb + (size_t)(s0 + sl) * DD;
        float prt = kr[lane] * p0 + kr[lane + 32] * p1;
#pragma unroll
        for (int off = 16; off; off >>= 1)
            prt += __shfl_xor_sync(0xffffffffu, prt, off);
        if (lane == 0)
            w[sl] = prt * SCALE + mask[(size_t)b * SS + s0 + sl];
    }
    __syncthreads();

    float l = w[t];
    red[t] = l; __syncthreads();
    for (int off = 128; off; off >>= 1) {
        if (t < off) red[t] = fmaxf(red[t], red[t + off]);
        __syncthreads();
    }
    float mloc = red[0];
    __syncthreads();

    float e = __expf(l - mloc);
    w[t] = e;
    red[t] = e; __syncthreads();
    for (int off = 128; off; off >>= 1) {
        if (t < off) red[t] += red[t + off];
        __syncthreads();
    }
    float esum = red[0];
    __syncthreads();

    int dh = t & 63, sg = t >> 6;
    const float* src2 = kb + (size_t)(s0 + sg) * DD + dh;
    float acc = 0.0f;
#pragma unroll 16
    for (int i = 0; i < CHS / 4; i++)
        acc += w[sg + 4 * i] * src2[(size_t)4 * i * DD];
    red[t] = acc; __syncthreads();
    if (t < 64)
        part[((size_t)bh * NCH + ch) * DHH + t] =
            red[t] + red[t + 64] + red[t + 128] + red[t + 192];
    if (t == 0) {
        mstat[((size_t)bh * NCH + ch) * 2]     = mloc;
        mstat[((size_t)bh * NCH + ch) * 2 + 1] = esum;
    }
}

// ---------------- reduce partials with global rescale -----------------------
__global__ void __launch_bounds__(64)
poolred_kernel(const float* __restrict__ part, const float* __restrict__ mstat,
               float* __restrict__ out)
{
    int bh = blockIdx.x, t = threadIdx.x;
    float ml[NCH], ss[NCH];
    float gmax = -1e30f;
#pragma unroll
    for (int c = 0; c < NCH; c++) {
        ml[c] = mstat[((size_t)bh * NCH + c) * 2];
        ss[c] = mstat[((size_t)bh * NCH + c) * 2 + 1];
        gmax = fmaxf(gmax, ml[c]);
    }
    float denom = 0.0f, acc = 0.0f;
#pragma unroll
    for (int c = 0; c < NCH; c++) {
        float f = __expf(ml[c] - gmax);
        denom += ss[c] * f;
        acc += part[((size_t)bh * NCH + c) * DHH + t] * f;
    }
    out[(size_t)bh * DHH + t] = acc / denom;
}

// ---------------------------------------------------------------------------
extern "C" void kernel_launch(void* const* d_in, const int* in_sizes, int n_in,
                              void* d_out, int out_size)
{
    const float* hs   = (const float*)d_in[0];
    const float* mask = (const float*)d_in[1];
    const float* Wq   = (const float*)d_in[2];
    const float* bq   = (const float*)d_in[3];
    const float* Wqa  = (const float*)d_in[4];
    const float* bqa  = (const float*)d_in[5];
    const float* Wk   = (const float*)d_in[6];
    const float* bk   = (const float*)d_in[7];
    const float* Wt   = (const float*)d_in[8];
    const float* bt   = (const float*)d_in[9];
    float* out = (float*)d_out;

    float *q, *k, *qlt, *partp, *mstat, *pq, *pk;
    __half *hsh, *qh, *wq, *wk, *wt, *wtb;
    cudaGetSymbolAddress((void**)&q,  g_q);
    cudaGetSymbolAddress((void**)&k,  g_k);
    cudaGetSymbolAddress((void**)&qlt, g_qlt);
    cudaGetSymbolAddress((void**)&partp, g_part);
    cudaGetSymbolAddress((void**)&mstat, g_mstat);
    cudaGetSymbolAddress((void**)&pq, g_pq);
    cudaGetSymbolAddress((void**)&pk, g_pk);
    cudaGetSymbolAddress((void**)&hsh, g_hsh);
    cudaGetSymbolAddress((void**)&qh, g_qh);
    cudaGetSymbolAddress((void**)&wq, g_wq);
    cudaGetSymbolAddress((void**)&wk, g_wk);
    cudaGetSymbolAddress((void**)&wt, g_wt);
    cudaGetSymbolAddress((void**)&wtb, g_wtb);

    cudaFuncSetAttribute(qlogits_kernel,
                         cudaFuncAttributeMaxDynamicSharedMemorySize, 65536);
    cudaFuncSetAttribute(gemm_tc,
                         cudaFuncAttributeMaxDynamicSharedMemorySize, SMEMB);

    const int conv_blocks = (MM * DD / 4) / 256;   // 16384
    dim3 wgrid(DD / 32, DD / 32);
    dim3 ggrid(DD / 128, MM / 128);                // (8, 128)
    dim3 pgrid(NCH, Bb * HH);                      // (8, 128)
    dim3 sgrid(DD * DD / 1024, Bb);                // (1024, 8)

    // conversions
    conv_half<<<conv_blocks, 256>>>(hs, hsh);
    conv_w<<<wgrid, 256>>>(Wq, wq);
    conv_w<<<wgrid, 256>>>(Wk, wk);
    conv_w<<<wgrid, 256>>>(Wt, wt);

    // q = hs @ Wq + bq (also emits qh fp16) ; k = hs @ Wk + bk
    gemm_tc<<<ggrid, 256, SMEMB>>>(hsh, wq, bq, q, q, qh, 0, 0);
    gemm_tc<<<ggrid, 256, SMEMB>>>(hsh, wk, bk, k, k, nullptr, 0, 0);

    // pooled_q path
    qlogits_kernel<<<MM / 32, 256, 65536>>>(Wqa, bqa, q, qlt);
    poolpart_kernel<<<pgrid, 256>>>(qlt, mask, q, partp, mstat);
    poolred_kernel<<<Bb * HH, 64>>>(partp, mstat, pq);

    // pooled_k path (fused logits + pool)
    qk_pool_kernel<<<pgrid, 256>>>(k, pq, mask, partp, mstat);
    poolred_kernel<<<Bb * HH, 64>>>(partp, mstat, pk);

    // per-batch scaled transform weight: W'_b = Wt^T * pk_b
    scale_wt_kernel<<<sgrid, 256>>>(wt, pk, wtb);

    // out = qh @ W'_b + bt + q
    gemm_tc<<<ggrid, 256, SMEMB>>>(qh, wtb, bt, q, out, nullptr, 1, DD * DD);
}